// round 14
// baseline (speedup 1.0000x reference)
#include <cuda_runtime.h>
#include <cstdint>

// QuantileLoss: mean over [N,5] loss built from preds[N,5], target[N,3].
// R14: R12 body (128-thr blocks, 16KB cp.async tile — plateau: 75.5% DRAM)
//      + sync-free L2 prefetch one wave ahead (cp.async.bulk.prefetch.L2):
//      wave k prefetches wave k+1's tiles into L2 (28MB/wave << 126MB L2),
//      so demand loads hit L2 (234cyc) instead of DRAM (577cyc) while the
//      prefetch stream keeps DRAM busy with zero completion dependencies.

__global__ void zero_out_kernel(float* out) {
    if (threadIdx.x == 0) out[0] = 0.0f;
}

__device__ __forceinline__ void cp_async16(uint32_t saddr, const void* gptr) {
    asm volatile("cp.async.cg.shared.global [%0], [%1], 16;\n"
                 :: "r"(saddr), "l"(gptr));
}

__device__ __forceinline__ void l2_prefetch_bulk(const void* gptr, uint32_t bytes) {
    asm volatile("cp.async.bulk.prefetch.L2.global [%0], %1;\n"
                 :: "l"(gptr), "r"(bytes) : "memory");
}

__device__ __forceinline__ float row_loss(
    float p0, float p1, float p2, float p3, float p4,
    float t0, float t1, float t2)
{
    float d0 = p0 - t0;
    float d1 = p1 - t1;
    float d2 = p2 - t2;
    float main_mse = d0 * d0 + d1 * d1 + d2 * d2;

    float pen = (p4 - t2) * 4.0f;

    float lo_th = t2 * 0.95f;
    float lo_d  = p3 - lo_th;
    float lower = (p3 > p2) ? pen : ((p3 > lo_th) ? 0.0f : lo_d * lo_d);

    float up_th = t2 * 1.05f;
    float up_d  = p4 - up_th;
    float upper = (p4 < p2) ? pen : ((p4 < up_th) ? 0.0f : up_d * up_d);

    return main_mse + lower + upper;
}

__device__ __forceinline__ float quad_rows(
    float4 p0, float4 p1, float4 p2, float4 p3, float4 p4,
    float4 g0, float4 g1, float4 g2)
{
    float s;
    s  = row_loss(p0.x, p0.y, p0.z, p0.w, p1.x, g0.x, g0.y, g0.z);
    s += row_loss(p1.y, p1.z, p1.w, p2.x, p2.y, g0.w, g1.x, g1.y);
    s += row_loss(p2.z, p2.w, p3.x, p3.y, p3.z, g1.z, g1.w, g2.x);
    s += row_loss(p3.w, p4.x, p4.y, p4.z, p4.w, g2.y, g2.z, g2.w);
    return s;
}

// One wave = 148 SMs * 12 resident blocks (16KB smem, 32 regs, 128 thr).
#define WAVE_BLOCKS 1776

// Tile: 128 quads (= 512 rows) per block of 128 threads.
// smem: 640 float4 preds + 384 float4 target = 1024 float4 = 16 KB exactly.
__global__ void __launch_bounds__(128)
quantile_loss_kernel(const float4* __restrict__ preds4,
                     const float4* __restrict__ tgt4,
                     const float*  __restrict__ preds,
                     const float*  __restrict__ target,
                     float* __restrict__ out,
                     int nquads, int n_rows, float inv_count)
{
    __shared__ float4 sh[1024];   // [0..639] preds, [640..1023] target

    const int tid = threadIdx.x;
    const int qb  = blockIdx.x << 7;   // 128 quads per block
    float s = 0.0f;

    // ---- sync-free L2 prefetch for the block one wave ahead ----
    if (tid == 0) {
        int pf = (int)blockIdx.x + WAVE_BLOCKS;
        int pqb = pf << 7;
        if (pqb + 128 <= nquads) {
            l2_prefetch_bulk(preds4 + (size_t)pqb * 5, 10240u);
            l2_prefetch_bulk(tgt4   + (size_t)pqb * 3,  6144u);
        }
    }

    if (qb + 128 <= nquads) {
        // ---- fast path: fully-coalesced cp.async staging ----
        uint32_t sbase = (uint32_t)__cvta_generic_to_shared(sh);
        const float4* pg = preds4 + (size_t)qb * 5;
        const float4* tg = tgt4   + (size_t)qb * 3;

        #pragma unroll
        for (int k = 0; k < 5; k++)
            cp_async16(sbase + (uint32_t)(k * 128 + tid) * 16u, pg + k * 128 + tid);
        #pragma unroll
        for (int k = 0; k < 3; k++)
            cp_async16(sbase + (uint32_t)(640 + k * 128 + tid) * 16u, tg + k * 128 + tid);

        asm volatile("cp.async.commit_group;\n" ::: "memory");
        asm volatile("cp.async.wait_group 0;\n" ::: "memory");
        __syncthreads();

        // strided smem reads: 80B / 48B lane strides are conflict-free
        float4 p0 = sh[tid * 5 + 0];
        float4 p1 = sh[tid * 5 + 1];
        float4 p2 = sh[tid * 5 + 2];
        float4 p3 = sh[tid * 5 + 3];
        float4 p4 = sh[tid * 5 + 4];
        float4 g0 = sh[640 + tid * 3 + 0];
        float4 g1 = sh[640 + tid * 3 + 1];
        float4 g2 = sh[640 + tid * 3 + 2];

        s = quad_rows(p0, p1, p2, p3, p4, g0, g1, g2);
    } else {
        // ---- partial tile: direct guarded loads (rare) ----
        int q = qb + tid;
        if (q < nquads) {
            float4 p0 = preds4[q * 5 + 0];
            float4 p1 = preds4[q * 5 + 1];
            float4 p2 = preds4[q * 5 + 2];
            float4 p3 = preds4[q * 5 + 3];
            float4 p4 = preds4[q * 5 + 4];
            float4 g0 = tgt4[q * 3 + 0];
            float4 g1 = tgt4[q * 3 + 1];
            float4 g2 = tgt4[q * 3 + 2];
            s = quad_rows(p0, p1, p2, p3, p4, g0, g1, g2);
        }
    }

    // tail rows (n_rows % 4) handled by one thread
    if (blockIdx.x == 0 && threadIdx.x == 0) {
        for (int r = nquads * 4; r < n_rows; r++) {
            s += row_loss(preds[r * 5 + 0], preds[r * 5 + 1], preds[r * 5 + 2],
                          preds[r * 5 + 3], preds[r * 5 + 4],
                          target[r * 3 + 0], target[r * 3 + 1], target[r * 3 + 2]);
        }
    }

    // intra-block reduce: warp shuffle -> smem (reuse tile) -> warp 0
    #pragma unroll
    for (int off = 16; off > 0; off >>= 1)
        s += __shfl_down_sync(0xFFFFFFFFu, s, off);

    __syncthreads();                      // all smem tile reads done
    float* ws = (float*)sh;               // reuse tile as warp-sum scratch
    int lane = tid & 31;
    int wid  = tid >> 5;
    if (lane == 0) ws[wid] = s;
    __syncthreads();

    if (wid == 0) {
        s = (lane < 4) ? ws[lane] : 0.0f;
        #pragma unroll
        for (int off = 2; off > 0; off >>= 1)
            s += __shfl_down_sync(0xFFFFFFFFu, s, off);
        if (lane == 0)
            atomicAdd(out, s * inv_count);
    }
}

extern "C" void kernel_launch(void* const* d_in, const int* in_sizes, int n_in,
                              void* d_out, int out_size)
{
    const float* preds  = (const float*)d_in[0];
    const float* target = (const float*)d_in[1];
    float* out = (float*)d_out;

    int n_rows = in_sizes[0] / 5;
    int nquads = n_rows / 4;
    float inv_count = 1.0f / (5.0f * (float)n_rows);

    zero_out_kernel<<<1, 32>>>(out);

    const int threads = 128;
    int blocks = (nquads + 127) / 128;
    if (blocks < 1) blocks = 1;

    quantile_loss_kernel<<<blocks, threads>>>(
        (const float4*)preds, (const float4*)target,
        preds, target, out, nquads, n_rows, inv_count);
}

// round 15
// speedup vs baseline: 1.1737x; 1.1737x over previous
#include <cuda_runtime.h>
#include <cstdint>

// QuantileLoss: mean over [N,5] loss built from preds[N,5], target[N,3].
// FINAL (= R4): cp.async-staged 32KB smem tiles for perfect per-LDG coalescing.
//   Direct loads have 80B/48B lane strides (~20 lines per LDG.128) -> L1tex
//   wavefront-limited at 72% DRAM; staging fixes that (76.5% DRAM, 6063 GB/s
//   = ~96% of the B300 LTS chip cap ~6300 B/cyc, which is path-independent).
//   Verified dead ends: double/ring buffering (occupancy or barrier cost),
//   persistent grids, TMA bulk (== cp.async at the cap), L2 prefetch (doubles
//   LTS traffic), single-node epilogues (any cross-block protocol costs 8% DRAM),
//   __ldcs, reg caps (occupancy was smem+reg co-limited).

__global__ void zero_out_kernel(float* out) {
    if (threadIdx.x == 0) out[0] = 0.0f;
}

__device__ __forceinline__ void cp_async16(uint32_t saddr, const void* gptr) {
    asm volatile("cp.async.cg.shared.global [%0], [%1], 16;\n"
                 :: "r"(saddr), "l"(gptr));
}

__device__ __forceinline__ float row_loss(
    float p0, float p1, float p2, float p3, float p4,
    float t0, float t1, float t2)
{
    float d0 = p0 - t0;
    float d1 = p1 - t1;
    float d2 = p2 - t2;
    float main_mse = d0 * d0 + d1 * d1 + d2 * d2;

    float pen = (p4 - t2) * 4.0f;

    float lo_th = t2 * 0.95f;
    float lo_d  = p3 - lo_th;
    float lower = (p3 > p2) ? pen : ((p3 > lo_th) ? 0.0f : lo_d * lo_d);

    float up_th = t2 * 1.05f;
    float up_d  = p4 - up_th;
    float upper = (p4 < p2) ? pen : ((p4 < up_th) ? 0.0f : up_d * up_d);

    return main_mse + lower + upper;
}

__device__ __forceinline__ float quad_rows(
    float4 p0, float4 p1, float4 p2, float4 p3, float4 p4,
    float4 g0, float4 g1, float4 g2)
{
    float s;
    s  = row_loss(p0.x, p0.y, p0.z, p0.w, p1.x, g0.x, g0.y, g0.z);
    s += row_loss(p1.y, p1.z, p1.w, p2.x, p2.y, g0.w, g1.x, g1.y);
    s += row_loss(p2.z, p2.w, p3.x, p3.y, p3.z, g1.z, g1.w, g2.x);
    s += row_loss(p3.w, p4.x, p4.y, p4.z, p4.w, g2.y, g2.z, g2.w);
    return s;
}

// Tile: 256 quads (= 1024 rows) per block of 256 threads.
// smem: 1280 float4 preds + 768 float4 target = 2048 float4 = 32 KB exactly.
__global__ void __launch_bounds__(256)
quantile_loss_kernel(const float4* __restrict__ preds4,
                     const float4* __restrict__ tgt4,
                     const float*  __restrict__ preds,
                     const float*  __restrict__ target,
                     float* __restrict__ out,
                     int nquads, int n_rows, float inv_count)
{
    __shared__ float4 sh[2048];   // [0..1279] preds, [1280..2047] target

    const int tid = threadIdx.x;
    const int qb  = blockIdx.x << 8;   // 256 quads per block
    float s = 0.0f;

    if (qb + 256 <= nquads) {
        // ---- fast path: fully-coalesced cp.async staging ----
        uint32_t sbase = (uint32_t)__cvta_generic_to_shared(sh);
        const float4* pg = preds4 + (size_t)qb * 5;
        const float4* tg = tgt4   + (size_t)qb * 3;

        #pragma unroll
        for (int k = 0; k < 5; k++)
            cp_async16(sbase + (uint32_t)(k * 256 + tid) * 16u, pg + k * 256 + tid);
        #pragma unroll
        for (int k = 0; k < 3; k++)
            cp_async16(sbase + (uint32_t)(1280 + k * 256 + tid) * 16u, tg + k * 256 + tid);

        asm volatile("cp.async.commit_group;\n" ::: "memory");
        asm volatile("cp.async.wait_group 0;\n" ::: "memory");
        __syncthreads();

        // strided smem reads: 80B / 48B lane strides are conflict-free
        float4 p0 = sh[tid * 5 + 0];
        float4 p1 = sh[tid * 5 + 1];
        float4 p2 = sh[tid * 5 + 2];
        float4 p3 = sh[tid * 5 + 3];
        float4 p4 = sh[tid * 5 + 4];
        float4 g0 = sh[1280 + tid * 3 + 0];
        float4 g1 = sh[1280 + tid * 3 + 1];
        float4 g2 = sh[1280 + tid * 3 + 2];

        s = quad_rows(p0, p1, p2, p3, p4, g0, g1, g2);
    } else {
        // ---- partial tile: direct guarded loads (rare) ----
        int q = qb + tid;
        if (q < nquads) {
            float4 p0 = preds4[q * 5 + 0];
            float4 p1 = preds4[q * 5 + 1];
            float4 p2 = preds4[q * 5 + 2];
            float4 p3 = preds4[q * 5 + 3];
            float4 p4 = preds4[q * 5 + 4];
            float4 g0 = tgt4[q * 3 + 0];
            float4 g1 = tgt4[q * 3 + 1];
            float4 g2 = tgt4[q * 3 + 2];
            s = quad_rows(p0, p1, p2, p3, p4, g0, g1, g2);
        }
    }

    // tail rows (n_rows % 4) handled by one thread
    if (blockIdx.x == 0 && threadIdx.x == 0) {
        for (int r = nquads * 4; r < n_rows; r++) {
            s += row_loss(preds[r * 5 + 0], preds[r * 5 + 1], preds[r * 5 + 2],
                          preds[r * 5 + 3], preds[r * 5 + 4],
                          target[r * 3 + 0], target[r * 3 + 1], target[r * 3 + 2]);
        }
    }

    // intra-block reduce: warp shuffle -> smem (reuse tile) -> warp 0
    #pragma unroll
    for (int off = 16; off > 0; off >>= 1)
        s += __shfl_down_sync(0xFFFFFFFFu, s, off);

    __syncthreads();                      // all smem tile reads done
    float* ws = (float*)sh;               // reuse tile as warp-sum scratch
    int lane = tid & 31;
    int wid  = tid >> 5;
    if (lane == 0) ws[wid] = s;
    __syncthreads();

    if (wid == 0) {
        s = (lane < 8) ? ws[lane] : 0.0f;
        #pragma unroll
        for (int off = 4; off > 0; off >>= 1)
            s += __shfl_down_sync(0xFFFFFFFFu, s, off);
        if (lane == 0)
            atomicAdd(out, s * inv_count);
    }
}

extern "C" void kernel_launch(void* const* d_in, const int* in_sizes, int n_in,
                              void* d_out, int out_size)
{
    const float* preds  = (const float*)d_in[0];
    const float* target = (const float*)d_in[1];
    float* out = (float*)d_out;

    int n_rows = in_sizes[0] / 5;
    int nquads = n_rows / 4;
    float inv_count = 1.0f / (5.0f * (float)n_rows);

    zero_out_kernel<<<1, 32>>>(out);

    const int threads = 256;
    int blocks = (nquads + 255) / 256;
    if (blocks < 1) blocks = 1;

    quantile_loss_kernel<<<blocks, threads>>>(
        (const float4*)preds, (const float4*)target,
        preds, target, out, nquads, n_rows, inv_count);
}